// round 14
// baseline (speedup 1.0000x reference)
#include <cuda_runtime.h>
#include <math.h>
#include <stdint.h>

#define B_  8
#define T_  12
#define N_  400
#define D_  128
#define H_  8
#define HD_ 16
#define U_  16
#define C_  64
#define FF_ 2048
#define BT_ (B_*T_)
#define M_  (BT_*N_)

__device__ float g_q1[M_*D_];
__device__ float g_k1[M_*D_];
__device__ float g_v1[M_*D_];
__device__ float g_q2[M_*D_];
__device__ float g_k2[M_*D_];
__device__ float g_v2[M_*D_];
__device__ float g_nodex[M_*D_];
__device__ float g_pk[BT_*C_*D_];
__device__ float g_pv[BT_*C_*D_];
__device__ float g_ao1[M_*D_];
__device__ float g_ao2[M_*D_];
__device__ float g_dtw[M_*D_];
__device__ float g_oa[M_*D_];
__device__ float g_extra[M_*D_];
__device__ float g_sen[N_*D_];
__device__ float g_esh[N_*D_];
__device__ float g_senx[N_*D_];
__device__ float g_out[M_*D_];
__device__ float g_oattn[M_*D_];
__device__ float g_spin[M_*D_];
__device__ float g_posT[N_*C_];

__device__ __forceinline__ void mma_tf32(float* d, const uint32_t* a, const uint32_t* b) {
    asm volatile(
        "mma.sync.aligned.m16n8k8.row.col.f32.tf32.tf32.f32 "
        "{%0,%1,%2,%3}, {%4,%5,%6,%7}, {%8,%9}, {%0,%1,%2,%3};\n"
        : "+f"(d[0]), "+f"(d[1]), "+f"(d[2]), "+f"(d[3])
        : "r"(a[0]), "r"(a[1]), "r"(a[2]), "r"(a[3]), "r"(b[0]), "r"(b[1]));
}

__device__ __forceinline__ int perm8(int b) { return 2 * (b & 3) + (b >> 2); }

// ------------------- batched tensor-core GEMM (projections) -------------------
struct GB {
    const float* A[8];
    const float* Bm[8];
    const float* bias[8];
    float* C[8];
};

template<bool RELU>
__global__ void __launch_bounds__(256) gemm_tc(GB gb, int M, int N, int K)
{
    __shared__ float As[2][128][20];
    __shared__ float Bs[2][16][136];
    const float* A    = gb.A[blockIdx.z];
    const float* B    = gb.Bm[blockIdx.z];
    const float* bias = gb.bias[blockIdx.z];
    float*       C    = gb.C[blockIdx.z];
    int tid = threadIdx.x;
    int lane = tid & 31;
    int warp = tid >> 5;
    int by = blockIdx.y * 128;
    int bx = blockIdx.x * 128;
    int wm = (warp & 1) * 64;
    int wn = (warp >> 1) * 32;
    float acc[4][4][4];
#pragma unroll
    for (int a = 0; a < 4; a++)
#pragma unroll
        for (int b = 0; b < 4; b++)
#pragma unroll
            for (int q = 0; q < 4; q++) acc[a][b][q] = 0.f;
    int m_a = tid >> 2;
    int k_a = (tid & 3) * 4;
    int k_b = tid >> 4;
    int n_b = (tid & 15) * 4;
    const float* Ap = A + (size_t)(by + m_a) * K + k_a;
    const float* Bp = B + (size_t)k_b * N + bx + n_b;
    float4 ra0 = *(const float4*)Ap;
    float4 ra1 = *(const float4*)(Ap + (size_t)64 * K);
    float4 rb0 = *(const float4*)Bp;
    float4 rb1 = *(const float4*)(Bp + 64);
    int ktiles = K >> 4;
    *(float4*)&As[0][m_a][k_a]      = ra0;
    *(float4*)&As[0][m_a + 64][k_a] = ra1;
    *(float4*)&Bs[0][k_b][n_b]      = rb0;
    *(float4*)&Bs[0][k_b][n_b + 64] = rb1;
    int c = lane & 3, r = lane >> 2;
    for (int t = 0; t < ktiles; t++) {
        __syncthreads();
        int st = t & 1;
        bool more = (t + 1 < ktiles);
        if (more) {
            const float* Ap2 = Ap + (t + 1) * 16;
            ra0 = *(const float4*)Ap2;
            ra1 = *(const float4*)(Ap2 + (size_t)64 * K);
            const float* Bp2 = Bp + (size_t)(t + 1) * 16 * N;
            rb0 = *(const float4*)Bp2;
            rb1 = *(const float4*)(Bp2 + 64);
        }
#pragma unroll
        for (int kk = 0; kk < 16; kk += 8) {
            uint32_t af[4][4], bf[4][2];
#pragma unroll
            for (int mi = 0; mi < 4; mi++) {
                int m = wm + mi * 16 + r;
                af[mi][0] = __float_as_uint(As[st][m][kk + c]);
                af[mi][1] = __float_as_uint(As[st][m + 8][kk + c]);
                af[mi][2] = __float_as_uint(As[st][m][kk + 4 + c]);
                af[mi][3] = __float_as_uint(As[st][m + 8][kk + 4 + c]);
            }
#pragma unroll
            for (int ni = 0; ni < 4; ni++) {
                int n = wn + ni * 8 + r;
                bf[ni][0] = __float_as_uint(Bs[st][kk + c][n]);
                bf[ni][1] = __float_as_uint(Bs[st][kk + 4 + c][n]);
            }
#pragma unroll
            for (int mi = 0; mi < 4; mi++)
#pragma unroll
                for (int ni = 0; ni < 4; ni++)
                    mma_tf32(acc[mi][ni], af[mi], bf[ni]);
        }
        if (more) {
            int s2 = st ^ 1;
            *(float4*)&As[s2][m_a][k_a]      = ra0;
            *(float4*)&As[s2][m_a + 64][k_a] = ra1;
            *(float4*)&Bs[s2][k_b][n_b]      = rb0;
            *(float4*)&Bs[s2][k_b][n_b + 64] = rb1;
        }
    }
    int g = lane >> 2, t2 = (lane & 3) * 2;
#pragma unroll
    for (int mi = 0; mi < 4; mi++) {
#pragma unroll
        for (int ni = 0; ni < 4; ni++) {
            int col = bx + wn + ni * 8 + t2;
            float b0 = bias[col], b1 = bias[col + 1];
            int row0 = by + wm + mi * 16 + g;
            float2 o;
            o.x = acc[mi][ni][0] + b0;
            o.y = acc[mi][ni][1] + b1;
            if (RELU) { o.x = fmaxf(o.x, 0.f); o.y = fmaxf(o.y, 0.f); }
            *(float2*)(C + (size_t)row0 * N + col) = o;
            o.x = acc[mi][ni][2] + b0;
            o.y = acc[mi][ni][3] + b1;
            if (RELU) { o.x = fmaxf(o.x, 0.f); o.y = fmaxf(o.y, 0.f); }
            *(float2*)(C + (size_t)(row0 + 8) * N + col) = o;
        }
    }
}

// ------------------- fused feed-forward: C = relu(A@W1+b1)@W2+b2 -------------------
#define FFS_AS   0
#define FFS_HS   (128*136)
#define FFS_WS   (2*128*136)
#define FFS_TOT  (2*128*136 + 2*16*136)

__device__ __forceinline__ void ff_gemm_tile(
    const float* __restrict__ Asrc, const float* __restrict__ Wst,
    float acc[4][4][4], int ktbase, int wm, int wn, int g, int c)
{
#pragma unroll
    for (int kk = 0; kk < 16; kk += 8) {
        uint32_t af[4][4], bf[4][2];
#pragma unroll
        for (int mi = 0; mi < 4; mi++) {
            int r0 = wm + mi * 16 + g;
            uint2 p0 = *(const uint2*)(Asrc + (size_t)r0 * 136 + ktbase + kk + 2 * c);
            uint2 p1 = *(const uint2*)(Asrc + (size_t)(r0 + 8) * 136 + ktbase + kk + 2 * c);
            af[mi][0] = p0.x; af[mi][1] = p1.x; af[mi][2] = p0.y; af[mi][3] = p1.y;
        }
#pragma unroll
        for (int ni = 0; ni < 4; ni++) {
            int n = wn + ni * 8 + g;
            bf[ni][0] = __float_as_uint(Wst[(size_t)(kk + c) * 136 + n]);
            bf[ni][1] = __float_as_uint(Wst[(size_t)(kk + 4 + c) * 136 + n]);
        }
#pragma unroll
        for (int mi = 0; mi < 4; mi++)
#pragma unroll
            for (int ni = 0; ni < 4; ni++)
                mma_tf32(acc[mi][ni], af[mi], bf[ni]);
    }
}

__global__ void __launch_bounds__(256) ff_fused(
    const float* __restrict__ A, const float* __restrict__ W1,
    const float* __restrict__ b1, const float* __restrict__ W2,
    const float* __restrict__ b2, float* __restrict__ C)
{
    extern __shared__ float fs[];
    float* As = fs + FFS_AS;
    float* Hs = fs + FFS_HS;
    float* Ws = fs + FFS_WS;
    int tid = threadIdx.x;
    int lane = tid & 31;
    int warp = tid >> 5;
    int by = blockIdx.x * 128;
    int wm = (warp & 1) * 64;
    int wn = (warp >> 1) * 32;
    int g = lane >> 2, c = lane & 3, t2 = c * 2;

    {   // stage A rows once (k-pair-permuted layout)
        int row = tid >> 1;
        int kb = (tid & 1) * 64;
        const float* Ap = A + (size_t)(by + row) * D_ + kb;
        float* dst = As + (size_t)row * 136 + kb;
#pragma unroll
        for (int j = 0; j < 8; j++) {
            float4 lo = *(const float4*)(Ap + j * 8);
            float4 hi = *(const float4*)(Ap + j * 8 + 4);
            *(float2*)(dst + j * 8 + 0) = make_float2(lo.x, hi.x);
            *(float2*)(dst + j * 8 + 2) = make_float2(lo.y, hi.y);
            *(float2*)(dst + j * 8 + 4) = make_float2(lo.z, hi.z);
            *(float2*)(dst + j * 8 + 6) = make_float2(lo.w, hi.w);
        }
    }

    float oacc[4][4][4];
#pragma unroll
    for (int a = 0; a < 4; a++)
#pragma unroll
        for (int b = 0; b < 4; b++)
#pragma unroll
            for (int q = 0; q < 4; q++) oacc[a][b][q] = 0.f;

    int k_b = tid >> 4;
    int n_b = (tid & 15) * 4;

    for (int f = 0; f < 16; f++) {
        // GEMM1: h = A @ W1[:, f*128 ..]
        float hacc[4][4][4];
#pragma unroll
        for (int a = 0; a < 4; a++)
#pragma unroll
            for (int b = 0; b < 4; b++)
#pragma unroll
                for (int q = 0; q < 4; q++) hacc[a][b][q] = 0.f;

        const float* W1p = W1 + (size_t)k_b * FF_ + f * 128 + n_b;
        float4 rb0 = *(const float4*)W1p;
        float4 rb1 = *(const float4*)(W1p + 64);
        *(float4*)&Ws[(size_t)k_b * 136 + n_b]      = rb0;
        *(float4*)&Ws[(size_t)k_b * 136 + n_b + 64] = rb1;

        for (int t = 0; t < 8; t++) {
            __syncthreads();
            int st = t & 1;
            bool more = (t < 7);
            if (more) {
                const float* p = W1p + (size_t)(t + 1) * 16 * FF_;
                rb0 = *(const float4*)p;
                rb1 = *(const float4*)(p + 64);
            }
            ff_gemm_tile(As, Ws + (size_t)st * 16 * 136, hacc, t * 16, wm, wn, g, c);
            if (more) {
                int s2 = st ^ 1;
                *(float4*)&Ws[((size_t)s2 * 16 + k_b) * 136 + n_b]      = rb0;
                *(float4*)&Ws[((size_t)s2 * 16 + k_b) * 136 + n_b + 64] = rb1;
            }
        }

        // epilogue: bias + relu -> Hs (k-pair-permuted)
        {
            int p0 = perm8(t2);
            int p1 = perm8(t2 + 1);
#pragma unroll
            for (int mi = 0; mi < 4; mi++) {
#pragma unroll
                for (int ni = 0; ni < 4; ni++) {
                    int colbase = wn + ni * 8;
                    float bb0 = b1[f * 128 + colbase + t2];
                    float bb1 = b1[f * 128 + colbase + t2 + 1];
                    int r0 = wm + mi * 16 + g;
                    Hs[(size_t)r0 * 136 + colbase + p0]       = fmaxf(hacc[mi][ni][0] + bb0, 0.f);
                    Hs[(size_t)r0 * 136 + colbase + p1]       = fmaxf(hacc[mi][ni][1] + bb1, 0.f);
                    Hs[(size_t)(r0 + 8) * 136 + colbase + p0] = fmaxf(hacc[mi][ni][2] + bb0, 0.f);
                    Hs[(size_t)(r0 + 8) * 136 + colbase + p1] = fmaxf(hacc[mi][ni][3] + bb1, 0.f);
                }
            }
        }

        // GEMM2: out += h @ W2[f*128 .., :]
        const float* W2p = W2 + (size_t)(f * 128 + k_b) * D_ + n_b;
        rb0 = *(const float4*)W2p;
        rb1 = *(const float4*)(W2p + 64);
        __syncthreads();
        *(float4*)&Ws[(size_t)k_b * 136 + n_b]      = rb0;
        *(float4*)&Ws[(size_t)k_b * 136 + n_b + 64] = rb1;

        for (int t = 0; t < 8; t++) {
            __syncthreads();
            int st = t & 1;
            bool more = (t < 7);
            if (more) {
                const float* p = W2p + (size_t)(t + 1) * 16 * D_;
                rb0 = *(const float4*)p;
                rb1 = *(const float4*)(p + 64);
            }
            ff_gemm_tile(Hs, Ws + (size_t)st * 16 * 136, oacc, t * 16, wm, wn, g, c);
            if (more) {
                int s2 = st ^ 1;
                *(float4*)&Ws[((size_t)s2 * 16 + k_b) * 136 + n_b]      = rb0;
                *(float4*)&Ws[((size_t)s2 * 16 + k_b) * 136 + n_b + 64] = rb1;
            }
        }
    }

#pragma unroll
    for (int mi = 0; mi < 4; mi++) {
#pragma unroll
        for (int ni = 0; ni < 4; ni++) {
            int col = wn + ni * 8 + t2;
            float bb0 = b2[col], bb1 = b2[col + 1];
            int row0 = by + wm + mi * 16 + g;
            *(float2*)(C + (size_t)row0 * D_ + col) =
                make_float2(oacc[mi][ni][0] + bb0, oacc[mi][ni][1] + bb1);
            *(float2*)(C + (size_t)(row0 + 8) * D_ + col) =
                make_float2(oacc[mi][ni][2] + bb0, oacc[mi][ni][3] + bb1);
        }
    }
}

// ------------------- small fp32 SGEMM (sen path) -------------------
template<bool RELU>
__global__ void __launch_bounds__(256) gemm_bias(
    const float* __restrict__ A, const float* __restrict__ B,
    const float* __restrict__ bias, float* __restrict__ C,
    int M, int N, int K)
{
    __shared__ float As[8][128];
    __shared__ float Bs[8][128];
    int tid = threadIdx.x;
    int bx = blockIdx.x * 128;
    int by = blockIdx.y * 128;
    int arow = tid >> 1, acol = (tid & 1) * 4;
    int brow = tid >> 5, bcol = (tid & 31) * 4;
    int tr = (tid >> 4) * 8, tc = (tid & 15) * 8;
    float acc[8][8];
#pragma unroll
    for (int i = 0; i < 8; i++)
#pragma unroll
        for (int j = 0; j < 8; j++) acc[i][j] = 0.f;
    int garow = by + arow;
    const float* Aptr = A + (size_t)garow * K + acol;
    const float* Bptr = B + (size_t)brow * N + bx + bcol;
    for (int k0 = 0; k0 < K; k0 += 8) {
        float4 av = make_float4(0.f, 0.f, 0.f, 0.f);
        if (garow < M) av = *(const float4*)(Aptr + k0);
        As[acol + 0][arow] = av.x;
        As[acol + 1][arow] = av.y;
        As[acol + 2][arow] = av.z;
        As[acol + 3][arow] = av.w;
        float4 bv = *(const float4*)(Bptr + (size_t)k0 * N);
        *(float4*)&Bs[brow][bcol] = bv;
        __syncthreads();
#pragma unroll
        for (int k = 0; k < 8; k++) {
            float ra[8], rb[8];
#pragma unroll
            for (int i = 0; i < 8; i++) ra[i] = As[k][tr + i];
#pragma unroll
            for (int j = 0; j < 8; j++) rb[j] = Bs[k][tc + j];
#pragma unroll
            for (int i = 0; i < 8; i++)
#pragma unroll
                for (int j = 0; j < 8; j++)
                    acc[i][j] += ra[i] * rb[j];
        }
        __syncthreads();
    }
#pragma unroll
    for (int i = 0; i < 8; i++) {
        int r = by + tr + i;
        if (r >= M) break;
        float* Cp = C + (size_t)r * N + bx + tc;
#pragma unroll
        for (int j = 0; j < 8; j += 4) {
            float4 v;
            v.x = acc[i][j + 0] + bias[bx + tc + j + 0];
            v.y = acc[i][j + 1] + bias[bx + tc + j + 1];
            v.z = acc[i][j + 2] + bias[bx + tc + j + 2];
            v.w = acc[i][j + 3] + bias[bx + tc + j + 3];
            if (RELU) {
                v.x = fmaxf(v.x, 0.f); v.y = fmaxf(v.y, 0.f);
                v.z = fmaxf(v.z, 0.f); v.w = fmaxf(v.w, 0.f);
            }
            *(float4*)(Cp + j) = v;
        }
    }
}

// ------------------- adaptive avg pool -------------------
__global__ void __launch_bounds__(128) pool_kernel(
    const float* __restrict__ K, const float* __restrict__ V,
    float* __restrict__ PK, float* __restrict__ PV)
{
    int d = threadIdx.x;
    int c = blockIdx.x % C_;
    int bt = blockIdx.x / C_;
    int s = (c * N_) / C_;
    int e = ((c + 1) * N_ + C_ - 1) / C_;
    float w = 1.f / (float)(e - s);
    const float* Kb = K + (size_t)bt * N_ * D_ + d;
    const float* Vb = V + (size_t)bt * N_ * D_ + d;
    float sk = 0.f, sv = 0.f;
    for (int n = s; n < e; n++) {
        sk += Kb[(size_t)n * D_];
        sv += Vb[(size_t)n * D_];
    }
    PK[((size_t)bt * C_ + c) * D_ + d] = sk * w;
    PV[((size_t)bt * C_ + c) * D_ + d] = sv * w;
}

__global__ void pos_transpose_kernel(const float* __restrict__ pos, float* __restrict__ posT)
{
    int c = threadIdx.x;
    int q = blockIdx.x;
    posT[(size_t)c * N_ + q] = pos[(size_t)q * C_ + c];
}

// ------------------- tensor-core full attention (dtw) -------------------
#define AF_KS_OFF   0
#define AF_VS_OFF   (400*24)
#define AF_PS_OFF   (400*24 + 200*40)
#define AF_SMEM_W   (400*24 + 200*40 + 8*16*68)

template<int NMAX>
__device__ __forceinline__ void af_chunk(
    int kb, const float* __restrict__ Ks, const float* __restrict__ Vs,
    float* __restrict__ Pw, const uint32_t aq[2][4], float oacc[2][4],
    float& rs_g, float& rs_g8, int g, int c, int t2)
{
    float sacc[NMAX][4];
#pragma unroll
    for (int ni = 0; ni < NMAX; ni++)
#pragma unroll
        for (int r = 0; r < 4; r++) sacc[ni][r] = 0.f;
#pragma unroll
    for (int ni = 0; ni < NMAX; ni++) {
        int keyrow = kb + ni * 8 + g;
#pragma unroll
        for (int s = 0; s < 2; s++) {
            uint2 bf = *(const uint2*)&Ks[keyrow * 24 + 8 * s + 2 * c];
            uint32_t bfr[2] = { bf.x, bf.y };
            mma_tf32(sacc[ni], aq[s], bfr);
        }
    }
#pragma unroll
    for (int ni = 0; ni < NMAX; ni++) {
        float p0 = __expf(sacc[ni][0]);
        float p1 = __expf(sacc[ni][1]);
        float p2 = __expf(sacc[ni][2]);
        float p3 = __expf(sacc[ni][3]);
        rs_g  += p0 + p1;
        rs_g8 += p2 + p3;
        *(float2*)&Pw[g * 68 + ni * 8 + t2]       = make_float2(p0, p1);
        *(float2*)&Pw[(g + 8) * 68 + ni * 8 + t2] = make_float2(p2, p3);
    }
    __syncwarp();
#pragma unroll
    for (int ks = 0; ks < NMAX; ks++) {
        uint32_t ap[4];
        ap[0] = __float_as_uint(Pw[g * 68 + ks * 8 + c]);
        ap[1] = __float_as_uint(Pw[(g + 8) * 68 + ks * 8 + c]);
        ap[2] = __float_as_uint(Pw[g * 68 + ks * 8 + c + 4]);
        ap[3] = __float_as_uint(Pw[(g + 8) * 68 + ks * 8 + c + 4]);
        int pairbase = ((kb >> 3) + ks) * 4 + c;
#pragma unroll
        for (int nv = 0; nv < 2; nv++) {
            uint2 bf = *(const uint2*)&Vs[pairbase * 40 + 2 * (nv * 8 + g)];
            uint32_t bfr[2] = { bf.x, bf.y };
            mma_tf32(oacc[nv], ap, bfr);
        }
    }
    __syncwarp();
}

__global__ void __launch_bounds__(256) attn_full_mma(
    const float* __restrict__ Q, const float* __restrict__ K,
    const float* __restrict__ V, float* __restrict__ O)
{
    extern __shared__ float smx[];
    float* Ks = smx + AF_KS_OFF;
    float* Vs = smx + AF_VS_OFF;
    int tid = threadIdx.x;
    int lane = tid & 31;
    int warp = tid >> 5;
    int bt = blockIdx.y >> 3;
    int h = blockIdx.y & 7;
    int qt = blockIdx.x;
    const float* Kb = K + (size_t)bt * N_ * D_ + h * HD_;
    const float* Vb = V + (size_t)bt * N_ * D_ + h * HD_;
    for (int i = tid; i < N_ * 16; i += 256) {
        int n = i >> 4, d = i & 15;
        int kp = 8 * (d >> 3) + 2 * (d & 3) + ((d & 7) >> 2);
        Ks[n * 24 + kp] = Kb[(size_t)n * D_ + d];
        int vpair = (n >> 3) * 4 + (n & 3);
        int velem = (n & 7) >> 2;
        Vs[vpair * 40 + 2 * d + velem] = Vb[(size_t)n * D_ + d];
    }
    __syncthreads();
    int qbase = qt * 128 + warp * 16;
    if (qbase >= N_) return;
    float* Pw = smx + AF_PS_OFF + warp * 16 * 68;
    int g = lane >> 2, c = lane & 3;
    int t2 = c * 2;
    const float* Qp = Q + ((size_t)bt * N_ + qbase) * D_ + h * HD_;
    uint32_t aq[2][4];
#pragma unroll
    for (int s = 0; s < 2; s++) {
        aq[s][0] = __float_as_uint(Qp[(size_t)g * D_ + 8 * s + c] * 0.25f);
        aq[s][1] = __float_as_uint(Qp[(size_t)(g + 8) * D_ + 8 * s + c] * 0.25f);
        aq[s][2] = __float_as_uint(Qp[(size_t)g * D_ + 8 * s + c + 4] * 0.25f);
        aq[s][3] = __float_as_uint(Qp[(size_t)(g + 8) * D_ + 8 * s + c + 4] * 0.25f);
    }
    float oacc[2][4];
#pragma unroll
    for (int nv = 0; nv < 2; nv++)
#pragma unroll
        for (int r = 0; r < 4; r++) oacc[nv][r] = 0.f;
    float rs_g = 0.f, rs_g8 = 0.f;
#pragma unroll 1
    for (int chunk = 0; chunk < 6; chunk++)
        af_chunk<8>(chunk * 64, Ks, Vs, Pw, aq, oacc, rs_g, rs_g8, g, c, t2);
    af_chunk<2>(384, Ks, Vs, Pw, aq, oacc, rs_g, rs_g8, g, c, t2);
    rs_g  += __shfl_xor_sync(0xffffffffu, rs_g, 1);
    rs_g  += __shfl_xor_sync(0xffffffffu, rs_g, 2);
    rs_g8 += __shfl_xor_sync(0xffffffffu, rs_g8, 1);
    rs_g8 += __shfl_xor_sync(0xffffffffu, rs_g8, 2);
    float inv_g = 1.f / rs_g;
    float inv_g8 = 1.f / rs_g8;
    float* Op = O + ((size_t)bt * N_ + qbase) * D_ + h * HD_;
#pragma unroll
    for (int nv = 0; nv < 2; nv++) {
        *(float2*)(Op + (size_t)g * D_ + nv * 8 + t2) =
            make_float2(oacc[nv][0] * inv_g, oacc[nv][1] * inv_g);
        *(float2*)(Op + (size_t)(g + 8) * D_ + nv * 8 + t2) =
            make_float2(oacc[nv][2] * inv_g8, oacc[nv][3] * inv_g8);
    }
}

// ------------------- pooled attention -------------------
__global__ void __launch_bounds__(256) attn_pool_kernel(
    const float* __restrict__ Q, const float* __restrict__ K,
    const float* __restrict__ V, const float* __restrict__ posT,
    float* __restrict__ O)
{
    __shared__ float Ks[C_ * HD_];
    __shared__ float Vs[C_ * HD_];
    int bt = blockIdx.x >> 3;
    int h = blockIdx.x & 7;
    const float* Kb = K + (size_t)bt * C_ * D_ + h * HD_;
    const float* Vb = V + (size_t)bt * C_ * D_ + h * HD_;
    for (int i = threadIdx.x; i < C_ * HD_; i += 256) {
        int c = i >> 4, d = i & 15;
        Ks[i] = Kb[(size_t)c * D_ + d];
        Vs[i] = Vb[(size_t)c * D_ + d];
    }
    __syncthreads();
    for (int q = threadIdx.x; q < N_; q += 256) {
        const float* Qp = Q + ((size_t)bt * N_ + q) * D_ + h * HD_;
        float qr[16];
#pragma unroll
        for (int i = 0; i < 16; i += 4) {
            float4 t = *(const float4*)(Qp + i);
            qr[i + 0] = t.x * 0.25f; qr[i + 1] = t.y * 0.25f;
            qr[i + 2] = t.z * 0.25f; qr[i + 3] = t.w * 0.25f;
        }
        float ssum = 0.f;
        float acc[16];
#pragma unroll
        for (int d = 0; d < 16; d++) acc[d] = 0.f;
        for (int c = 0; c < C_; c++) {
            const float4* kr = (const float4*)&Ks[c * 16];
            const float4* vr = (const float4*)&Vs[c * 16];
            float4 k0 = kr[0], k1 = kr[1], k2 = kr[2], k3 = kr[3];
            float sc = posT[(size_t)c * N_ + q];
            sc = fmaf(qr[0], k0.x, sc);  sc = fmaf(qr[1], k0.y, sc);
            sc = fmaf(qr[2], k0.z, sc);  sc = fmaf(qr[3], k0.w, sc);
            sc = fmaf(qr[4], k1.x, sc);  sc = fmaf(qr[5], k1.y, sc);
            sc = fmaf(qr[6], k1.z, sc);  sc = fmaf(qr[7], k1.w, sc);
            sc = fmaf(qr[8], k2.x, sc);  sc = fmaf(qr[9], k2.y, sc);
            sc = fmaf(qr[10], k2.z, sc); sc = fmaf(qr[11], k2.w, sc);
            sc = fmaf(qr[12], k3.x, sc); sc = fmaf(qr[13], k3.y, sc);
            sc = fmaf(qr[14], k3.z, sc); sc = fmaf(qr[15], k3.w, sc);
            float p = __expf(sc);
            ssum += p;
            float4 v0 = vr[0], v1 = vr[1], v2 = vr[2], v3 = vr[3];
            acc[0]  = fmaf(p, v0.x, acc[0]);  acc[1]  = fmaf(p, v0.y, acc[1]);
            acc[2]  = fmaf(p, v0.z, acc[2]);  acc[3]  = fmaf(p, v0.w, acc[3]);
            acc[4]  = fmaf(p, v1.x, acc[4]);  acc[5]  = fmaf(p, v1.y, acc[5]);
            acc[6]  = fmaf(p, v1.z, acc[6]);  acc[7]  = fmaf(p, v1.w, acc[7]);
            acc[8]  = fmaf(p, v2.x, acc[8]);  acc[9]  = fmaf(p, v2.y, acc[9]);
            acc[10] = fmaf(p, v2.z, acc[10]); acc[11] = fmaf(p, v2.w, acc[11]);
            acc[12] = fmaf(p, v3.x, acc[12]); acc[13] = fmaf(p, v3.y, acc[13]);
            acc[14] = fmaf(p, v3.z, acc[14]); acc[15] = fmaf(p, v3.w, acc[15]);
        }
        float inv = 1.f / ssum;
        float* Op = O + ((size_t)bt * N_ + q) * D_ + h * HD_;
#pragma unroll
        for (int i = 0; i < 16; i += 4) {
            float4 t;
            t.x = acc[i + 0] * inv; t.y = acc[i + 1] * inv;
            t.z = acc[i + 2] * inv; t.w = acc[i + 3] * inv;
            *(float4*)(Op + i) = t;
        }
    }
}

__device__ __forceinline__ float warp_sum(float v) {
#pragma unroll
    for (int o = 16; o; o >>= 1) v += __shfl_xor_sync(0xffffffffu, v, o);
    return v;
}

// ------------------- GEANet node path -------------------
__global__ void __launch_bounds__(256) gea_node_kernel(
    const float* __restrict__ nodex, const float* __restrict__ W,
    const float* __restrict__ Wb, float* __restrict__ outp)
{
    __shared__ float w0[16][16], w1[16][16], b0s[16], b1s[16];
    int tid = threadIdx.x;
    w0[tid >> 4][tid & 15] = W[tid];
    w1[tid >> 4][tid & 15] = W[256 + tid];
    if (tid < 16) { b0s[tid] = Wb[tid]; b1s[tid] = Wb[16 + tid]; }
    __syncthreads();
    int g = blockIdx.x * 32 + (tid >> 3);
    int h = tid & 7;
    if (g >= B_ * N_ * T_) return;
    int b = g / (N_ * T_);
    int rem = g - b * (N_ * T_);
    int n = rem / T_;
    int l = rem - n * T_;
    const float* ip = nodex + ((size_t)(b * T_ + l) * N_ + n) * D_ + h * U_;
    float a[16];
#pragma unroll
    for (int i = 0; i < 16; i += 4) {
        float4 t = *(const float4*)(ip + i);
        a[i] = t.x; a[i + 1] = t.y; a[i + 2] = t.z; a[i + 3] = t.w;
    }
    float e[16];
#pragma unroll
    for (int u2 = 0; u2 < 16; u2++) {
        float s = b0s[u2];
#pragma unroll
        for (int u = 0; u < 16; u++) s += a[u] * w0[u][u2];
        e[u2] = __expf(s);
    }
    float r[16]; float rs = 0.f;
#pragma unroll
    for (int u2 = 0; u2 < 16; u2++) {
        float d = e[u2];
        d += __shfl_xor_sync(0xffffffffu, d, 1);
        d += __shfl_xor_sync(0xffffffffu, d, 2);
        d += __shfl_xor_sync(0xffffffffu, d, 4);
        r[u2] = e[u2] / d;
        rs += r[u2];
    }
    float inv = 1.f / rs;
    int idx = n * T_ + l;
    int l2 = idx / N_;
    int n2 = idx - l2 * N_;
    float* op = outp + ((size_t)(b * T_ + l2) * N_ + n2) * D_ + h * U_;
#pragma unroll
    for (int u2 = 0; u2 < 16; u2 += 4) {
        float4 t;
        float vv[4];
#pragma unroll
        for (int jj = 0; jj < 4; jj++) {
            float s = b1s[u2 + jj];
#pragma unroll
            for (int u = 0; u < 16; u++) s += (r[u] * inv) * w1[u][u2 + jj];
            vv[jj] = s;
        }
        t.x = vv[0]; t.y = vv[1]; t.z = vv[2]; t.w = vv[3];
        *(float4*)(op + u2) = t;
    }
}

// ------------------- GEANet edge path -------------------
__global__ void __launch_bounds__(256) gea_edge_kernel(
    const float* __restrict__ esh, const float* __restrict__ W,
    const float* __restrict__ Wb, float* __restrict__ senx, float* __restrict__ osen)
{
    __shared__ float w0[16][16], w1[16][16], b0s[16], b1s[16];
    int tid = threadIdx.x;
    w0[tid >> 4][tid & 15] = W[tid];
    w1[tid >> 4][tid & 15] = W[256 + tid];
    if (tid < 16) { b0s[tid] = Wb[tid]; b1s[tid] = Wb[16 + tid]; }
    __syncthreads();
    int g = blockIdx.x * 32 + (tid >> 3);
    int h = tid & 7;
    if (g >= N_) return;
    const float* ip = esh + (size_t)g * D_;
    float a[16];
#pragma unroll
    for (int u = 0; u < 16; u++) a[u] = ip[u * 8 + h];
    float e[16];
#pragma unroll
    for (int u2 = 0; u2 < 16; u2++) {
        float s = b0s[u2];
#pragma unroll
        for (int u = 0; u < 16; u++) s += a[u] * w0[u][u2];
        e[u2] = __expf(s);
    }
    float r[16]; float rs = 0.f;
#pragma unroll
    for (int u2 = 0; u2 < 16; u2++) {
        float d = e[u2];
        d += __shfl_xor_sync(0xffffffffu, d, 1);
        d += __shfl_xor_sync(0xffffffffu, d, 2);
        d += __shfl_xor_sync(0xffffffffu, d, 4);
        r[u2] = e[u2] / d;
        rs += r[u2];
    }
    float inv = 1.f / rs;
    float* sp = senx + (size_t)g * D_ + h * U_;
    float* op = osen + (size_t)g * D_ + h * U_;
#pragma unroll
    for (int u2 = 0; u2 < 16; u2++) {
        float s = b1s[u2];
#pragma unroll
        for (int u = 0; u < 16; u++) s += (r[u] * inv) * w1[u][u2];
        sp[u2] = s;
        op[u2] = s;
    }
}

// ------------------- LN kernels -------------------
__global__ void ln_plain_kernel(const float* __restrict__ in,
    const float* __restrict__ gamma, const float* __restrict__ beta,
    float* __restrict__ out, int rows)
{
    int w = (blockIdx.x * blockDim.x + threadIdx.x) >> 5;
    int lane = threadIdx.x & 31;
    if (w >= rows) return;
    size_t base = (size_t)w * D_ + lane * 4;
    float4 v4 = *(const float4*)(in + base);
    float v[4] = { v4.x, v4.y, v4.z, v4.w };
    float s = warp_sum(v[0] + v[1] + v[2] + v[3]);
    float mean = s * (1.f / D_);
    float q = 0.f;
#pragma unroll
    for (int i = 0; i < 4; i++) { float d = v[i] - mean; q += d * d; }
    q = warp_sum(q);
    float rstd = rsqrtf(q * (1.f / D_) + 1e-5f);
    float4 o;
    o.x = (v[0] - mean) * rstd * gamma[lane * 4 + 0] + beta[lane * 4 + 0];
    o.y = (v[1] - mean) * rstd * gamma[lane * 4 + 1] + beta[lane * 4 + 1];
    o.z = (v[2] - mean) * rstd * gamma[lane * 4 + 2] + beta[lane * 4 + 2];
    o.w = (v[3] - mean) * rstd * gamma[lane * 4 + 3] + beta[lane * 4 + 3];
    *(float4*)(out + base) = o;
}

__global__ void ln4_kernel(const float* __restrict__ x, const float* __restrict__ a,
    const float* __restrict__ b2, const float* __restrict__ c,
    const float* __restrict__ gamma, const float* __restrict__ beta,
    float* __restrict__ out, int rows)
{
    int w = (blockIdx.x * blockDim.x + threadIdx.x) >> 5;
    int lane = threadIdx.x & 31;
    if (w >= rows) return;
    size_t base = (size_t)w * D_ + lane * 4;
    float4 vx = *(const float4*)(x + base);
    float4 va = *(const float4*)(a + base);
    float4 vb = *(const float4*)(b2 + base);
    float4 vc = *(const float4*)(c + base);
    float v[4] = { vx.x + va.x + vb.x + vc.x, vx.y + va.y + vb.y + vc.y,
                   vx.z + va.z + vb.z + vc.z, vx.w + va.w + vb.w + vc.w };
    float s = warp_sum(v[0] + v[1] + v[2] + v[3]);
    float mean = s * (1.f / D_);
    float q = 0.f;
#pragma unroll
    for (int i = 0; i < 4; i++) { float d = v[i] - mean; q += d * d; }
    q = warp_sum(q);
    float rstd = rsqrtf(q * (1.f / D_) + 1e-5f);
    float4 o;
    o.x = (v[0] - mean) * rstd * gamma[lane * 4 + 0] + beta[lane * 4 + 0];
    o.y = (v[1] - mean) * rstd * gamma[lane * 4 + 1] + beta[lane * 4 + 1];
    o.z = (v[2] - mean) * rstd * gamma[lane * 4 + 2] + beta[lane * 4 + 2];
    o.w = (v[3] - mean) * rstd * gamma[lane * 4 + 3] + beta[lane * 4 + 3];
    *(float4*)(out + base) = o;
}

__global__ void ln2mul_kernel(const float* __restrict__ ff, const float* __restrict__ res,
    const float* __restrict__ gamma, const float* __restrict__ beta,
    const float* __restrict__ senx, float* __restrict__ oattn, float* __restrict__ spin,
    int rows)
{
    int w = (blockIdx.x * blockDim.x + threadIdx.x) >> 5;
    int lane = threadIdx.x & 31;
    if (w >= rows) return;
    size_t base = (size_t)w * D_ + lane * 4;
    int n = w % N_;
    float4 vf = *(const float4*)(ff + base);
    float4 vr = *(const float4*)(res + base);
    float v[4] = { vf.x + vr.x, vf.y + vr.y, vf.z + vr.z, vf.w + vr.w };
    float s = warp_sum(v[0] + v[1] + v[2] + v[3]);
    float mean = s * (1.f / D_);
    float q = 0.f;
#pragma unroll
    for (int i = 0; i < 4; i++) { float d = v[i] - mean; q += d * d; }
    q = warp_sum(q);
    float rstd = rsqrtf(q * (1.f / D_) + 1e-5f);
    float4 se = *(const float4*)(senx + (size_t)n * D_ + lane * 4);
    float o[4];
#pragma unroll
    for (int i = 0; i < 4; i++)
        o[i] = (v[i] - mean) * rstd * gamma[lane * 4 + i] + beta[lane * 4 + i];
    float4 ov = { o[0], o[1], o[2], o[3] };
    *(float4*)(oattn + base) = ov;
    float4 sv = { o[0] * se.x, o[1] * se.y, o[2] * se.z, o[3] * se.w };
    *(float4*)(spin + base) = sv;
}

__global__ void ln_final_kernel(const float* __restrict__ ff2, const float* __restrict__ oattn,
    const float* __restrict__ gamma, const float* __restrict__ beta,
    float* __restrict__ out, int rows)
{
    int w = (blockIdx.x * blockDim.x + threadIdx.x) >> 5;
    int lane = threadIdx.x & 31;
    if (w >= rows) return;
    size_t base = (size_t)w * D_ + lane * 4;
    float4 vf = *(const float4*)(ff2 + base);
    float v[4] = { vf.x, vf.y, vf.z, vf.w };
    float s = warp_sum(v[0] + v[1] + v[2] + v[3]);
    float mean = s * (1.f / D_);
    float q = 0.f;
#pragma unroll
    for (int i = 0; i < 4; i++) { float d = v[i] - mean; q += d * d; }
    q = warp_sum(q);
    float rstd = rsqrtf(q * (1.f / D_) + 1e-5f);
    float4 va = *(const float4*)(oattn + base);
    float4 o;
    o.x = va.x + (v[0] - mean) * rstd * gamma[lane * 4 + 0] + beta[lane * 4 + 0];
    o.y = va.y + (v[1] - mean) * rstd * gamma[lane * 4 + 1] + beta[lane * 4 + 1];
    o.z = va.z + (v[2] - mean) * rstd * gamma[lane * 4 + 2] + beta[lane * 4 + 2];
    o.w = va.w + (v[3] - mean) * rstd * gamma[lane * 4 + 3] + beta[lane * 4 + 3];
    *(float4*)(out + base) = o;
}

// ------------------- host launch -------------------
extern "C" void kernel_launch(void* const* d_in, const int* in_sizes, int n_in,
                              void* d_out, int out_size)
{
    const float* x            = (const float*)d_in[0];
    const float* spatial_emb  = (const float*)d_in[1];
    const float* dtw_qkv_w    = (const float*)d_in[2];
    const float* dtw_qkv_b    = (const float*)d_in[3];
    const float* dtw_out_w    = (const float*)d_in[4];
    const float* dtw_out_b    = (const float*)d_in[5];
    const float* attn_qkv_w   = (const float*)d_in[6];
    const float* attn_qkv_b   = (const float*)d_in[7];
    const float* attn_out_w   = (const float*)d_in[8];
    const float* attn_out_b   = (const float*)d_in[9];
    const float* adp_pos      = (const float*)d_in[10];
    const float* gea_share_w  = (const float*)d_in[11];
    const float* gea_share_b  = (const float*)d_in[12];
    const float* gea_node_w   = (const float*)d_in[13];
    const float* gea_node_b   = (const float*)d_in[14];
    const float* gea_edge_w   = (const float*)d_in[15];
    const float* gea_edge_b   = (const float*)d_in[16];
    const float* spatial_w    = (const float*)d_in[17];
    const float* spatial_b    = (const float*)d_in[18];
    const float* ff1_w1       = (const float*)d_in[19];
    const float* ff1_b1       = (const float*)d_in[20];
    const float* ff1_w2       = (const float*)d_in[21];
    const float* ff1_b2       = (const float*)d_in[22];
    const float* ff2_w1       = (const float*)d_in[23];
    const float* ff2_b1       = (const float*)d_in[24];
    const float* ff2_w2       = (const float*)d_in[25];
    const float* ff2_b2       = (const float*)d_in[26];
    const float* ln_s         = (const float*)d_in[27];
    const float* ln_b         = (const float*)d_in[28];

    float* o_main = (float*)d_out;
    float* o_sen  = o_main + (size_t)M_ * D_;

    float *q1, *k1, *v1, *q2, *k2, *v2, *nodex, *pk, *pv, *ao1, *ao2;
    float *dtw, *oa, *extra, *sen, *esh, *senx, *outb, *oattn, *spin, *posT;
    cudaGetSymbolAddress((void**)&q1, g_q1);
    cudaGetSymbolAddress((void**)&k1, g_k1);
    cudaGetSymbolAddress((void**)&v1, g_v1);
    cudaGetSymbolAddress((void**)&q2, g_q2);
    cudaGetSymbolAddress((void**)&k2, g_k2);
    cudaGetSymbolAddress((void**)&v2, g_v2);
    cudaGetSymbolAddress((void**)&nodex, g_nodex);
    cudaGetSymbolAddress((void**)&pk, g_pk);
    cudaGetSymbolAddress((void**)&pv, g_pv);
    cudaGetSymbolAddress((void**)&ao1, g_ao1);
    cudaGetSymbolAddress((void**)&ao2, g_ao2);
    cudaGetSymbolAddress((void**)&dtw, g_dtw);
    cudaGetSymbolAddress((void**)&oa, g_oa);
    cudaGetSymbolAddress((void**)&extra, g_extra);
    cudaGetSymbolAddress((void**)&sen, g_sen);
    cudaGetSymbolAddress((void**)&esh, g_esh);
    cudaGetSymbolAddress((void**)&senx, g_senx);
    cudaGetSymbolAddress((void**)&outb, g_out);
    cudaGetSymbolAddress((void**)&oattn, g_oattn);
    cudaGetSymbolAddress((void**)&spin, g_spin);
    cudaGetSymbolAddress((void**)&posT, g_posT);

    int lnBlocksM = (M_ * 32 + 255) / 256;
    int lnBlocksS = (N_ * 32 + 255) / 256;
    dim3 gS(1, (N_ + 127) / 128);

    pos_transpose_kernel<<<N_, C_>>>(adp_pos, posT);

    {
        GB gb = {};
        for (int z = 0; z < 7; z++) gb.A[z] = x;
        gb.Bm[0] = dtw_qkv_w + 0 * D_ * D_;  gb.bias[0] = dtw_qkv_b + 0 * D_;  gb.C[0] = q1;
        gb.Bm[1] = dtw_qkv_w + 1 * D_ * D_;  gb.bias[1] = dtw_qkv_b + 1 * D_;  gb.C[1] = k1;
        gb.Bm[2] = dtw_qkv_w + 2 * D_ * D_;  gb.bias[2] = dtw_qkv_b + 2 * D_;  gb.C[2] = v1;
        gb.Bm[3] = attn_qkv_w + 0 * D_ * D_; gb.bias[3] = attn_qkv_b + 0 * D_; gb.C[3] = q2;
        gb.Bm[4] = attn_qkv_w + 1 * D_ * D_; gb.bias[4] = attn_qkv_b + 1 * D_; gb.C[4] = k2;
        gb.Bm[5] = attn_qkv_w + 2 * D_ * D_; gb.bias[5] = attn_qkv_b + 2 * D_; gb.C[5] = v2;
        gb.Bm[6] = gea_share_w;              gb.bias[6] = gea_share_b;         gb.C[6] = nodex;
        gemm_tc<false><<<dim3(1, M_ / 128, 7), 256>>>(gb, M_, D_, D_);
    }

    pool_kernel<<<BT_ * C_, 128>>>(k2, v2, pk, pv);

    cudaFuncSetAttribute(attn_full_mma, cudaFuncAttributeMaxDynamicSharedMemorySize,
                         AF_SMEM_W * 4);
    attn_full_mma<<<dim3(4, BT_ * H_), 256, AF_SMEM_W * 4>>>(q1, k1, v1, ao1);
    attn_pool_kernel<<<BT_ * H_, 256>>>(q2, pk, pv, posT, ao2);

    {
        GB gb = {};
        gb.A[0] = ao1; gb.Bm[0] = dtw_out_w;  gb.bias[0] = dtw_out_b;  gb.C[0] = dtw;
        gb.A[1] = ao2; gb.Bm[1] = attn_out_w; gb.bias[1] = attn_out_b; gb.C[1] = oa;
        gemm_tc<false><<<dim3(1, M_ / 128, 2), 256>>>(gb, M_, D_, D_);
    }

    gea_node_kernel<<<(B_ * N_ * T_ + 31) / 32, 256>>>(nodex, gea_node_w, gea_node_b, extra);

    gemm_bias<false><<<gS, 256>>>(spatial_emb, spatial_w, spatial_b, esh, N_, D_, D_);
    ln_plain_kernel<<<lnBlocksS, 256>>>(esh, ln_s + 3 * D_, ln_b + 3 * D_, sen, N_);
    gemm_bias<false><<<gS, 256>>>(sen, gea_share_w, gea_share_b, esh, N_, D_, D_);
    gea_edge_kernel<<<(N_ + 31) / 32, 256>>>(esh, gea_edge_w, gea_edge_b, senx, o_sen);

    ln4_kernel<<<lnBlocksM, 256>>>(x, dtw, oa, extra, ln_s, ln_b, outb, M_);

    // fused FF1 + ln2(+spatial mul)
    cudaFuncSetAttribute(ff_fused, cudaFuncAttributeMaxDynamicSharedMemorySize, FFS_TOT * 4);
    ff_fused<<<M_ / 128, 256, FFS_TOT * 4>>>(outb, ff1_w1, ff1_b1, ff1_w2, ff1_b2, ao1);
    ln2mul_kernel<<<lnBlocksM, 256>>>(ao1, outb, ln_s + D_, ln_b + D_, senx, oattn, spin, M_);

    // fused FF2 + spatial_norm + final add
    ff_fused<<<M_ / 128, 256, FFS_TOT * 4>>>(spin, ff2_w1, ff2_b1, ff2_w2, ff2_b2, ao2);
    ln_final_kernel<<<lnBlocksM, 256>>>(ao2, oattn, ln_s + 2 * D_, ln_b + 2 * D_, o_main, M_);
}

// round 16
// speedup vs baseline: 1.0744x; 1.0744x over previous
#include <cuda_runtime.h>
#include <math.h>
#include <stdint.h>

#define B_  8
#define T_  12
#define N_  400
#define D_  128
#define H_  8
#define HD_ 16
#define U_  16
#define C_  64
#define FF_ 2048
#define BT_ (B_*T_)
#define M_  (BT_*N_)

__device__ float g_q1[M_*D_];
__device__ float g_k1[M_*D_];
__device__ float g_v1[M_*D_];
__device__ float g_q2[M_*D_];
__device__ float g_k2[M_*D_];
__device__ float g_v2[M_*D_];
__device__ float g_nodex[M_*D_];
__device__ float g_pk[BT_*C_*D_];
__device__ float g_pv[BT_*C_*D_];
__device__ float g_ao1[M_*D_];
__device__ float g_ao2[M_*D_];
__device__ float g_dtw[M_*D_];
__device__ float g_oa[M_*D_];
__device__ float g_extra[M_*D_];
__device__ float g_sen[N_*D_];
__device__ float g_esh[N_*D_];
__device__ float g_senx[N_*D_];
__device__ float g_out[M_*D_];
__device__ float g_ff[M_*FF_];
__device__ float g_oattn[M_*D_];
__device__ float g_spin[M_*D_];
__device__ float g_posT[N_*C_];

__device__ __forceinline__ void mma_tf32(float* d, const uint32_t* a, const uint32_t* b) {
    asm volatile(
        "mma.sync.aligned.m16n8k8.row.col.f32.tf32.tf32.f32 "
        "{%0,%1,%2,%3}, {%4,%5,%6,%7}, {%8,%9}, {%0,%1,%2,%3};\n"
        : "+f"(d[0]), "+f"(d[1]), "+f"(d[2]), "+f"(d[3])
        : "r"(a[0]), "r"(a[1]), "r"(a[2]), "r"(a[3]), "r"(b[0]), "r"(b[1]));
}

// ------------------- batched tensor-core GEMM -------------------
struct GB {
    const float* A[8];
    const float* Bm[8];
    const float* bias[8];
    float* C[8];
};

template<bool RELU>
__global__ void __launch_bounds__(256) gemm_tc(GB gb, int M, int N, int K)
{
    __shared__ float As[2][128][20];
    __shared__ float Bs[2][16][136];
    const float* A    = gb.A[blockIdx.z];
    const float* B    = gb.Bm[blockIdx.z];
    const float* bias = gb.bias[blockIdx.z];
    float*       C    = gb.C[blockIdx.z];
    int tid = threadIdx.x;
    int lane = tid & 31;
    int warp = tid >> 5;
    int by = blockIdx.y * 128;
    int bx = blockIdx.x * 128;
    int wm = (warp & 1) * 64;
    int wn = (warp >> 1) * 32;
    float acc[4][4][4];
#pragma unroll
    for (int a = 0; a < 4; a++)
#pragma unroll
        for (int b = 0; b < 4; b++)
#pragma unroll
            for (int q = 0; q < 4; q++) acc[a][b][q] = 0.f;
    int m_a = tid >> 2;
    int k_a = (tid & 3) * 4;
    int k_b = tid >> 4;
    int n_b = (tid & 15) * 4;
    const float* Ap = A + (size_t)(by + m_a) * K + k_a;
    const float* Bp = B + (size_t)k_b * N + bx + n_b;
    float4 ra0 = *(const float4*)Ap;
    float4 ra1 = *(const float4*)(Ap + (size_t)64 * K);
    float4 rb0 = *(const float4*)Bp;
    float4 rb1 = *(const float4*)(Bp + 64);
    int ktiles = K >> 4;
    *(float4*)&As[0][m_a][k_a]      = ra0;
    *(float4*)&As[0][m_a + 64][k_a] = ra1;
    *(float4*)&Bs[0][k_b][n_b]      = rb0;
    *(float4*)&Bs[0][k_b][n_b + 64] = rb1;
    int c = lane & 3, r = lane >> 2;
    for (int t = 0; t < ktiles; t++) {
        __syncthreads();
        int st = t & 1;
        bool more = (t + 1 < ktiles);
        if (more) {
            const float* Ap2 = Ap + (t + 1) * 16;
            ra0 = *(const float4*)Ap2;
            ra1 = *(const float4*)(Ap2 + (size_t)64 * K);
            const float* Bp2 = Bp + (size_t)(t + 1) * 16 * N;
            rb0 = *(const float4*)Bp2;
            rb1 = *(const float4*)(Bp2 + 64);
        }
#pragma unroll
        for (int kk = 0; kk < 16; kk += 8) {
            uint32_t af[4][4], bf[4][2];
#pragma unroll
            for (int mi = 0; mi < 4; mi++) {
                int m = wm + mi * 16 + r;
                af[mi][0] = __float_as_uint(As[st][m][kk + c]);
                af[mi][1] = __float_as_uint(As[st][m + 8][kk + c]);
                af[mi][2] = __float_as_uint(As[st][m][kk + 4 + c]);
                af[mi][3] = __float_as_uint(As[st][m + 8][kk + 4 + c]);
            }
#pragma unroll
            for (int ni = 0; ni < 4; ni++) {
                int n = wn + ni * 8 + r;
                bf[ni][0] = __float_as_uint(Bs[st][kk + c][n]);
                bf[ni][1] = __float_as_uint(Bs[st][kk + 4 + c][n]);
            }
#pragma unroll
            for (int mi = 0; mi < 4; mi++)
#pragma unroll
                for (int ni = 0; ni < 4; ni++)
                    mma_tf32(acc[mi][ni], af[mi], bf[ni]);
        }
        if (more) {
            int s2 = st ^ 1;
            *(float4*)&As[s2][m_a][k_a]      = ra0;
            *(float4*)&As[s2][m_a + 64][k_a] = ra1;
            *(float4*)&Bs[s2][k_b][n_b]      = rb0;
            *(float4*)&Bs[s2][k_b][n_b + 64] = rb1;
        }
    }
    int g = lane >> 2, t2 = (lane & 3) * 2;
#pragma unroll
    for (int mi = 0; mi < 4; mi++) {
#pragma unroll
        for (int ni = 0; ni < 4; ni++) {
            int col = bx + wn + ni * 8 + t2;
            float b0 = bias[col], b1 = bias[col + 1];
            int row0 = by + wm + mi * 16 + g;
            float2 o;
            o.x = acc[mi][ni][0] + b0;
            o.y = acc[mi][ni][1] + b1;
            if (RELU) { o.x = fmaxf(o.x, 0.f); o.y = fmaxf(o.y, 0.f); }
            *(float2*)(C + (size_t)row0 * N + col) = o;
            o.x = acc[mi][ni][2] + b0;
            o.y = acc[mi][ni][3] + b1;
            if (RELU) { o.x = fmaxf(o.x, 0.f); o.y = fmaxf(o.y, 0.f); }
            *(float2*)(C + (size_t)(row0 + 8) * N + col) = o;
        }
    }
}

// ------------------- small fp32 SGEMM (sen path) -------------------
template<bool RELU>
__global__ void __launch_bounds__(256) gemm_bias(
    const float* __restrict__ A, const float* __restrict__ B,
    const float* __restrict__ bias, float* __restrict__ C,
    int M, int N, int K)
{
    __shared__ float As[8][128];
    __shared__ float Bs[8][128];
    int tid = threadIdx.x;
    int bx = blockIdx.x * 128;
    int by = blockIdx.y * 128;
    int arow = tid >> 1, acol = (tid & 1) * 4;
    int brow = tid >> 5, bcol = (tid & 31) * 4;
    int tr = (tid >> 4) * 8, tc = (tid & 15) * 8;
    float acc[8][8];
#pragma unroll
    for (int i = 0; i < 8; i++)
#pragma unroll
        for (int j = 0; j < 8; j++) acc[i][j] = 0.f;
    int garow = by + arow;
    const float* Aptr = A + (size_t)garow * K + acol;
    const float* Bptr = B + (size_t)brow * N + bx + bcol;
    for (int k0 = 0; k0 < K; k0 += 8) {
        float4 av = make_float4(0.f, 0.f, 0.f, 0.f);
        if (garow < M) av = *(const float4*)(Aptr + k0);
        As[acol + 0][arow] = av.x;
        As[acol + 1][arow] = av.y;
        As[acol + 2][arow] = av.z;
        As[acol + 3][arow] = av.w;
        float4 bv = *(const float4*)(Bptr + (size_t)k0 * N);
        *(float4*)&Bs[brow][bcol] = bv;
        __syncthreads();
#pragma unroll
        for (int k = 0; k < 8; k++) {
            float ra[8], rb[8];
#pragma unroll
            for (int i = 0; i < 8; i++) ra[i] = As[k][tr + i];
#pragma unroll
            for (int j = 0; j < 8; j++) rb[j] = Bs[k][tc + j];
#pragma unroll
            for (int i = 0; i < 8; i++)
#pragma unroll
                for (int j = 0; j < 8; j++)
                    acc[i][j] += ra[i] * rb[j];
        }
        __syncthreads();
    }
#pragma unroll
    for (int i = 0; i < 8; i++) {
        int r = by + tr + i;
        if (r >= M) break;
        float* Cp = C + (size_t)r * N + bx + tc;
#pragma unroll
        for (int j = 0; j < 8; j += 4) {
            float4 v;
            v.x = acc[i][j + 0] + bias[bx + tc + j + 0];
            v.y = acc[i][j + 1] + bias[bx + tc + j + 1];
            v.z = acc[i][j + 2] + bias[bx + tc + j + 2];
            v.w = acc[i][j + 3] + bias[bx + tc + j + 3];
            if (RELU) {
                v.x = fmaxf(v.x, 0.f); v.y = fmaxf(v.y, 0.f);
                v.z = fmaxf(v.z, 0.f); v.w = fmaxf(v.w, 0.f);
            }
            *(float4*)(Cp + j) = v;
        }
    }
}

// ------------------- adaptive avg pool -------------------
__global__ void __launch_bounds__(128) pool_kernel(
    const float* __restrict__ K, const float* __restrict__ V,
    float* __restrict__ PK, float* __restrict__ PV)
{
    int d = threadIdx.x;
    int c = blockIdx.x % C_;
    int bt = blockIdx.x / C_;
    int s = (c * N_) / C_;
    int e = ((c + 1) * N_ + C_ - 1) / C_;
    float w = 1.f / (float)(e - s);
    const float* Kb = K + (size_t)bt * N_ * D_ + d;
    const float* Vb = V + (size_t)bt * N_ * D_ + d;
    float sk = 0.f, sv = 0.f;
    for (int n = s; n < e; n++) {
        sk += Kb[(size_t)n * D_];
        sv += Vb[(size_t)n * D_];
    }
    PK[((size_t)bt * C_ + c) * D_ + d] = sk * w;
    PV[((size_t)bt * C_ + c) * D_ + d] = sv * w;
}

__global__ void pos_transpose_kernel(const float* __restrict__ pos, float* __restrict__ posT)
{
    int c = threadIdx.x;
    int q = blockIdx.x;
    posT[(size_t)c * N_ + q] = pos[(size_t)q * C_ + c];
}

// ------------------- tensor-core full attention (dtw) -------------------
#define AF_KS_OFF   0
#define AF_VS_OFF   (400*24)
#define AF_PS_OFF   (400*24 + 200*40)
#define AF_SMEM_W   (400*24 + 200*40 + 8*16*68)

template<int NMAX>
__device__ __forceinline__ void af_chunk(
    int kb, const float* __restrict__ Ks, const float* __restrict__ Vs,
    float* __restrict__ Pw, const uint32_t aq[2][4], float oacc[2][4],
    float& rs_g, float& rs_g8, int g, int c, int t2)
{
    float sacc[NMAX][4];
#pragma unroll
    for (int ni = 0; ni < NMAX; ni++)
#pragma unroll
        for (int r = 0; r < 4; r++) sacc[ni][r] = 0.f;
#pragma unroll
    for (int ni = 0; ni < NMAX; ni++) {
        int keyrow = kb + ni * 8 + g;
#pragma unroll
        for (int s = 0; s < 2; s++) {
            uint2 bf = *(const uint2*)&Ks[keyrow * 24 + 8 * s + 2 * c];
            uint32_t bfr[2] = { bf.x, bf.y };
            mma_tf32(sacc[ni], aq[s], bfr);
        }
    }
#pragma unroll
    for (int ni = 0; ni < NMAX; ni++) {
        float p0 = __expf(sacc[ni][0]);
        float p1 = __expf(sacc[ni][1]);
        float p2 = __expf(sacc[ni][2]);
        float p3 = __expf(sacc[ni][3]);
        rs_g  += p0 + p1;
        rs_g8 += p2 + p3;
        *(float2*)&Pw[g * 68 + ni * 8 + t2]       = make_float2(p0, p1);
        *(float2*)&Pw[(g + 8) * 68 + ni * 8 + t2] = make_float2(p2, p3);
    }
    __syncwarp();
#pragma unroll
    for (int ks = 0; ks < NMAX; ks++) {
        uint32_t ap[4];
        ap[0] = __float_as_uint(Pw[g * 68 + ks * 8 + c]);
        ap[1] = __float_as_uint(Pw[(g + 8) * 68 + ks * 8 + c]);
        ap[2] = __float_as_uint(Pw[g * 68 + ks * 8 + c + 4]);
        ap[3] = __float_as_uint(Pw[(g + 8) * 68 + ks * 8 + c + 4]);
        int pairbase = ((kb >> 3) + ks) * 4 + c;
#pragma unroll
        for (int nv = 0; nv < 2; nv++) {
            uint2 bf = *(const uint2*)&Vs[pairbase * 40 + 2 * (nv * 8 + g)];
            uint32_t bfr[2] = { bf.x, bf.y };
            mma_tf32(oacc[nv], ap, bfr);
        }
    }
    __syncwarp();
}

__global__ void __launch_bounds__(256) attn_full_mma(
    const float* __restrict__ Q, const float* __restrict__ K,
    const float* __restrict__ V, float* __restrict__ O)
{
    extern __shared__ float smx[];
    float* Ks = smx + AF_KS_OFF;
    float* Vs = smx + AF_VS_OFF;
    int tid = threadIdx.x;
    int lane = tid & 31;
    int warp = tid >> 5;
    int bt = blockIdx.y >> 3;
    int h = blockIdx.y & 7;
    int qt = blockIdx.x;
    const float* Kb = K + (size_t)bt * N_ * D_ + h * HD_;
    const float* Vb = V + (size_t)bt * N_ * D_ + h * HD_;
    for (int i = tid; i < N_ * 16; i += 256) {
        int n = i >> 4, d = i & 15;
        int kp = 8 * (d >> 3) + 2 * (d & 3) + ((d & 7) >> 2);
        Ks[n * 24 + kp] = Kb[(size_t)n * D_ + d];
        int vpair = (n >> 3) * 4 + (n & 3);
        int velem = (n & 7) >> 2;
        Vs[vpair * 40 + 2 * d + velem] = Vb[(size_t)n * D_ + d];
    }
    __syncthreads();
    int qbase = qt * 128 + warp * 16;
    if (qbase >= N_) return;
    float* Pw = smx + AF_PS_OFF + warp * 16 * 68;
    int g = lane >> 2, c = lane & 3;
    int t2 = c * 2;
    const float* Qp = Q + ((size_t)bt * N_ + qbase) * D_ + h * HD_;
    uint32_t aq[2][4];
#pragma unroll
    for (int s = 0; s < 2; s++) {
        aq[s][0] = __float_as_uint(Qp[(size_t)g * D_ + 8 * s + c] * 0.25f);
        aq[s][1] = __float_as_uint(Qp[(size_t)(g + 8) * D_ + 8 * s + c] * 0.25f);
        aq[s][2] = __float_as_uint(Qp[(size_t)g * D_ + 8 * s + c + 4] * 0.25f);
        aq[s][3] = __float_as_uint(Qp[(size_t)(g + 8) * D_ + 8 * s + c + 4] * 0.25f);
    }
    float oacc[2][4];
#pragma unroll
    for (int nv = 0; nv < 2; nv++)
#pragma unroll
        for (int r = 0; r < 4; r++) oacc[nv][r] = 0.f;
    float rs_g = 0.f, rs_g8 = 0.f;
#pragma unroll 1
    for (int chunk = 0; chunk < 6; chunk++)
        af_chunk<8>(chunk * 64, Ks, Vs, Pw, aq, oacc, rs_g, rs_g8, g, c, t2);
    af_chunk<2>(384, Ks, Vs, Pw, aq, oacc, rs_g, rs_g8, g, c, t2);
    rs_g  += __shfl_xor_sync(0xffffffffu, rs_g, 1);
    rs_g  += __shfl_xor_sync(0xffffffffu, rs_g, 2);
    rs_g8 += __shfl_xor_sync(0xffffffffu, rs_g8, 1);
    rs_g8 += __shfl_xor_sync(0xffffffffu, rs_g8, 2);
    float inv_g = 1.f / rs_g;
    float inv_g8 = 1.f / rs_g8;
    float* Op = O + ((size_t)bt * N_ + qbase) * D_ + h * HD_;
#pragma unroll
    for (int nv = 0; nv < 2; nv++) {
        *(float2*)(Op + (size_t)g * D_ + nv * 8 + t2) =
            make_float2(oacc[nv][0] * inv_g, oacc[nv][1] * inv_g);
        *(float2*)(Op + (size_t)(g + 8) * D_ + nv * 8 + t2) =
            make_float2(oacc[nv][2] * inv_g8, oacc[nv][3] * inv_g8);
    }
}

// ------------------- pooled attention -------------------
__global__ void __launch_bounds__(256) attn_pool_kernel(
    const float* __restrict__ Q, const float* __restrict__ K,
    const float* __restrict__ V, const float* __restrict__ posT,
    float* __restrict__ O)
{
    __shared__ float Ks[C_ * HD_];
    __shared__ float Vs[C_ * HD_];
    int bt = blockIdx.x >> 3;
    int h = blockIdx.x & 7;
    const float* Kb = K + (size_t)bt * C_ * D_ + h * HD_;
    const float* Vb = V + (size_t)bt * C_ * D_ + h * HD_;
    for (int i = threadIdx.x; i < C_ * HD_; i += 256) {
        int c = i >> 4, d = i & 15;
        Ks[i] = Kb[(size_t)c * D_ + d];
        Vs[i] = Vb[(size_t)c * D_ + d];
    }
    __syncthreads();
    for (int q = threadIdx.x; q < N_; q += 256) {
        const float* Qp = Q + ((size_t)bt * N_ + q) * D_ + h * HD_;
        float qr[16];
#pragma unroll
        for (int i = 0; i < 16; i += 4) {
            float4 t = *(const float4*)(Qp + i);
            qr[i + 0] = t.x * 0.25f; qr[i + 1] = t.y * 0.25f;
            qr[i + 2] = t.z * 0.25f; qr[i + 3] = t.w * 0.25f;
        }
        float ssum = 0.f;
        float acc[16];
#pragma unroll
        for (int d = 0; d < 16; d++) acc[d] = 0.f;
        for (int c = 0; c < C_; c++) {
            const float4* kr = (const float4*)&Ks[c * 16];
            const float4* vr = (const float4*)&Vs[c * 16];
            float4 k0 = kr[0], k1 = kr[1], k2 = kr[2], k3 = kr[3];
            float sc = posT[(size_t)c * N_ + q];
            sc = fmaf(qr[0], k0.x, sc);  sc = fmaf(qr[1], k0.y, sc);
            sc = fmaf(qr[2], k0.z, sc);  sc = fmaf(qr[3], k0.w, sc);
            sc = fmaf(qr[4], k1.x, sc);  sc = fmaf(qr[5], k1.y, sc);
            sc = fmaf(qr[6], k1.z, sc);  sc = fmaf(qr[7], k1.w, sc);
            sc = fmaf(qr[8], k2.x, sc);  sc = fmaf(qr[9], k2.y, sc);
            sc = fmaf(qr[10], k2.z, sc); sc = fmaf(qr[11], k2.w, sc);
            sc = fmaf(qr[12], k3.x, sc); sc = fmaf(qr[13], k3.y, sc);
            sc = fmaf(qr[14], k3.z, sc); sc = fmaf(qr[15], k3.w, sc);
            float p = __expf(sc);
            ssum += p;
            float4 v0 = vr[0], v1 = vr[1], v2 = vr[2], v3 = vr[3];
            acc[0]  = fmaf(p, v0.x, acc[0]);  acc[1]  = fmaf(p, v0.y, acc[1]);
            acc[2]  = fmaf(p, v0.z, acc[2]);  acc[3]  = fmaf(p, v0.w, acc[3]);
            acc[4]  = fmaf(p, v1.x, acc[4]);  acc[5]  = fmaf(p, v1.y, acc[5]);
            acc[6]  = fmaf(p, v1.z, acc[6]);  acc[7]  = fmaf(p, v1.w, acc[7]);
            acc[8]  = fmaf(p, v2.x, acc[8]);  acc[9]  = fmaf(p, v2.y, acc[9]);
            acc[10] = fmaf(p, v2.z, acc[10]); acc[11] = fmaf(p, v2.w, acc[11]);
            acc[12] = fmaf(p, v3.x, acc[12]); acc[13] = fmaf(p, v3.y, acc[13]);
            acc[14] = fmaf(p, v3.z, acc[14]); acc[15] = fmaf(p, v3.w, acc[15]);
        }
        float inv = 1.f / ssum;
        float* Op = O + ((size_t)bt * N_ + q) * D_ + h * HD_;
#pragma unroll
        for (int i = 0; i < 16; i += 4) {
            float4 t;
            t.x = acc[i + 0] * inv; t.y = acc[i + 1] * inv;
            t.z = acc[i + 2] * inv; t.w = acc[i + 3] * inv;
            *(float4*)(Op + i) = t;
        }
    }
}

__device__ __forceinline__ float warp_sum(float v) {
#pragma unroll
    for (int o = 16; o; o >>= 1) v += __shfl_xor_sync(0xffffffffu, v, o);
    return v;
}

// ------------------- GEANet node path -------------------
__global__ void __launch_bounds__(256) gea_node_kernel(
    const float* __restrict__ nodex, const float* __restrict__ W,
    const float* __restrict__ Wb, float* __restrict__ outp)
{
    __shared__ float w0[16][16], w1[16][16], b0s[16], b1s[16];
    int tid = threadIdx.x;
    w0[tid >> 4][tid & 15] = W[tid];
    w1[tid >> 4][tid & 15] = W[256 + tid];
    if (tid < 16) { b0s[tid] = Wb[tid]; b1s[tid] = Wb[16 + tid]; }
    __syncthreads();
    int g = blockIdx.x * 32 + (tid >> 3);
    int h = tid & 7;
    if (g >= B_ * N_ * T_) return;
    int b = g / (N_ * T_);
    int rem = g - b * (N_ * T_);
    int n = rem / T_;
    int l = rem - n * T_;
    const float* ip = nodex + ((size_t)(b * T_ + l) * N_ + n) * D_ + h * U_;
    float a[16];
#pragma unroll
    for (int i = 0; i < 16; i += 4) {
        float4 t = *(const float4*)(ip + i);
        a[i] = t.x; a[i + 1] = t.y; a[i + 2] = t.z; a[i + 3] = t.w;
    }
    float e[16];
#pragma unroll
    for (int u2 = 0; u2 < 16; u2++) {
        float s = b0s[u2];
#pragma unroll
        for (int u = 0; u < 16; u++) s += a[u] * w0[u][u2];
        e[u2] = __expf(s);
    }
    float r[16]; float rs = 0.f;
#pragma unroll
    for (int u2 = 0; u2 < 16; u2++) {
        float d = e[u2];
        d += __shfl_xor_sync(0xffffffffu, d, 1);
        d += __shfl_xor_sync(0xffffffffu, d, 2);
        d += __shfl_xor_sync(0xffffffffu, d, 4);
        r[u2] = e[u2] / d;
        rs += r[u2];
    }
    float inv = 1.f / rs;
    int idx = n * T_ + l;
    int l2 = idx / N_;
    int n2 = idx - l2 * N_;
    float* op = outp + ((size_t)(b * T_ + l2) * N_ + n2) * D_ + h * U_;
#pragma unroll
    for (int u2 = 0; u2 < 16; u2 += 4) {
        float4 t;
        float vv[4];
#pragma unroll
        for (int jj = 0; jj < 4; jj++) {
            float s = b1s[u2 + jj];
#pragma unroll
            for (int u = 0; u < 16; u++) s += (r[u] * inv) * w1[u][u2 + jj];
            vv[jj] = s;
        }
        t.x = vv[0]; t.y = vv[1]; t.z = vv[2]; t.w = vv[3];
        *(float4*)(op + u2) = t;
    }
}

// ------------------- GEANet edge path -------------------
__global__ void __launch_bounds__(256) gea_edge_kernel(
    const float* __restrict__ esh, const float* __restrict__ W,
    const float* __restrict__ Wb, float* __restrict__ senx, float* __restrict__ osen)
{
    __shared__ float w0[16][16], w1[16][16], b0s[16], b1s[16];
    int tid = threadIdx.x;
    w0[tid >> 4][tid & 15] = W[tid];
    w1[tid >> 4][tid & 15] = W[256 + tid];
    if (tid < 16) { b0s[tid] = Wb[tid]; b1s[tid] = Wb[16 + tid]; }
    __syncthreads();
    int g = blockIdx.x * 32 + (tid >> 3);
    int h = tid & 7;
    if (g >= N_) return;
    const float* ip = esh + (size_t)g * D_;
    float a[16];
#pragma unroll
    for (int u = 0; u < 16; u++) a[u] = ip[u * 8 + h];
    float e[16];
#pragma unroll
    for (int u2 = 0; u2 < 16; u2++) {
        float s = b0s[u2];
#pragma unroll
        for (int u = 0; u < 16; u++) s += a[u] * w0[u][u2];
        e[u2] = __expf(s);
    }
    float r[16]; float rs = 0.f;
#pragma unroll
    for (int u2 = 0; u2 < 16; u2++) {
        float d = e[u2];
        d += __shfl_xor_sync(0xffffffffu, d, 1);
        d += __shfl_xor_sync(0xffffffffu, d, 2);
        d += __shfl_xor_sync(0xffffffffu, d, 4);
        r[u2] = e[u2] / d;
        rs += r[u2];
    }
    float inv = 1.f / rs;
    float* sp = senx + (size_t)g * D_ + h * U_;
    float* op = osen + (size_t)g * D_ + h * U_;
#pragma unroll
    for (int u2 = 0; u2 < 16; u2++) {
        float s = b1s[u2];
#pragma unroll
        for (int u = 0; u < 16; u++) s += (r[u] * inv) * w1[u][u2];
        sp[u2] = s;
        op[u2] = s;
    }
}

// ------------------- LN kernels -------------------
__global__ void ln_plain_kernel(const float* __restrict__ in,
    const float* __restrict__ gamma, const float* __restrict__ beta,
    float* __restrict__ out, int rows)
{
    int w = (blockIdx.x * blockDim.x + threadIdx.x) >> 5;
    int lane = threadIdx.x & 31;
    if (w >= rows) return;
    size_t base = (size_t)w * D_ + lane * 4;
    float4 v4 = *(const float4*)(in + base);
    float v[4] = { v4.x, v4.y, v4.z, v4.w };
    float s = warp_sum(v[0] + v[1] + v[2] + v[3]);
    float mean = s * (1.f / D_);
    float q = 0.f;
#pragma unroll
    for (int i = 0; i < 4; i++) { float d = v[i] - mean; q += d * d; }
    q = warp_sum(q);
    float rstd = rsqrtf(q * (1.f / D_) + 1e-5f);
    float4 o;
    o.x = (v[0] - mean) * rstd * gamma[lane * 4 + 0] + beta[lane * 4 + 0];
    o.y = (v[1] - mean) * rstd * gamma[lane * 4 + 1] + beta[lane * 4 + 1];
    o.z = (v[2] - mean) * rstd * gamma[lane * 4 + 2] + beta[lane * 4 + 2];
    o.w = (v[3] - mean) * rstd * gamma[lane * 4 + 3] + beta[lane * 4 + 3];
    *(float4*)(out + base) = o;
}

__global__ void ln4_kernel(const float* __restrict__ x, const float* __restrict__ a,
    const float* __restrict__ b2, const float* __restrict__ c,
    const float* __restrict__ gamma, const float* __restrict__ beta,
    float* __restrict__ out, int rows)
{
    int w = (blockIdx.x * blockDim.x + threadIdx.x) >> 5;
    int lane = threadIdx.x & 31;
    if (w >= rows) return;
    size_t base = (size_t)w * D_ + lane * 4;
    float4 vx = *(const float4*)(x + base);
    float4 va = *(const float4*)(a + base);
    float4 vb = *(const float4*)(b2 + base);
    float4 vc = *(const float4*)(c + base);
    float v[4] = { vx.x + va.x + vb.x + vc.x, vx.y + va.y + vb.y + vc.y,
                   vx.z + va.z + vb.z + vc.z, vx.w + va.w + vb.w + vc.w };
    float s = warp_sum(v[0] + v[1] + v[2] + v[3]);
    float mean = s * (1.f / D_);
    float q = 0.f;
#pragma unroll
    for (int i = 0; i < 4; i++) { float d = v[i] - mean; q += d * d; }
    q = warp_sum(q);
    float rstd = rsqrtf(q * (1.f / D_) + 1e-5f);
    float4 o;
    o.x = (v[0] - mean) * rstd * gamma[lane * 4 + 0] + beta[lane * 4 + 0];
    o.y = (v[1] - mean) * rstd * gamma[lane * 4 + 1] + beta[lane * 4 + 1];
    o.z = (v[2] - mean) * rstd * gamma[lane * 4 + 2] + beta[lane * 4 + 2];
    o.w = (v[3] - mean) * rstd * gamma[lane * 4 + 3] + beta[lane * 4 + 3];
    *(float4*)(out + base) = o;
}

__global__ void ln2mul_kernel(const float* __restrict__ ff, const float* __restrict__ res,
    const float* __restrict__ gamma, const float* __restrict__ beta,
    const float* __restrict__ senx, float* __restrict__ oattn, float* __restrict__ spin,
    int rows)
{
    int w = (blockIdx.x * blockDim.x + threadIdx.x) >> 5;
    int lane = threadIdx.x & 31;
    if (w >= rows) return;
    size_t base = (size_t)w * D_ + lane * 4;
    int n = w % N_;
    float4 vf = *(const float4*)(ff + base);
    float4 vr = *(const float4*)(res + base);
    float v[4] = { vf.x + vr.x, vf.y + vr.y, vf.z + vr.z, vf.w + vr.w };
    float s = warp_sum(v[0] + v[1] + v[2] + v[3]);
    float mean = s * (1.f / D_);
    float q = 0.f;
#pragma unroll
    for (int i = 0; i < 4; i++) { float d = v[i] - mean; q += d * d; }
    q = warp_sum(q);
    float rstd = rsqrtf(q * (1.f / D_) + 1e-5f);
    float4 se = *(const float4*)(senx + (size_t)n * D_ + lane * 4);
    float o[4];
#pragma unroll
    for (int i = 0; i < 4; i++)
        o[i] = (v[i] - mean) * rstd * gamma[lane * 4 + i] + beta[lane * 4 + i];
    float4 ov = { o[0], o[1], o[2], o[3] };
    *(float4*)(oattn + base) = ov;
    float4 sv = { o[0] * se.x, o[1] * se.y, o[2] * se.z, o[3] * se.w };
    *(float4*)(spin + base) = sv;
}

__global__ void ln_final_kernel(const float* __restrict__ ff2, const float* __restrict__ oattn,
    const float* __restrict__ gamma, const float* __restrict__ beta,
    float* __restrict__ out, int rows)
{
    int w = (blockIdx.x * blockDim.x + threadIdx.x) >> 5;
    int lane = threadIdx.x & 31;
    if (w >= rows) return;
    size_t base = (size_t)w * D_ + lane * 4;
    float4 vf = *(const float4*)(ff2 + base);
    float v[4] = { vf.x, vf.y, vf.z, vf.w };
    float s = warp_sum(v[0] + v[1] + v[2] + v[3]);
    float mean = s * (1.f / D_);
    float q = 0.f;
#pragma unroll
    for (int i = 0; i < 4; i++) { float d = v[i] - mean; q += d * d; }
    q = warp_sum(q);
    float rstd = rsqrtf(q * (1.f / D_) + 1e-5f);
    float4 va = *(const float4*)(oattn + base);
    float4 o;
    o.x = va.x + (v[0] - mean) * rstd * gamma[lane * 4 + 0] + beta[lane * 4 + 0];
    o.y = va.y + (v[1] - mean) * rstd * gamma[lane * 4 + 1] + beta[lane * 4 + 1];
    o.z = va.z + (v[2] - mean) * rstd * gamma[lane * 4 + 2] + beta[lane * 4 + 2];
    o.w = va.w + (v[3] - mean) * rstd * gamma[lane * 4 + 3] + beta[lane * 4 + 3];
    *(float4*)(out + base) = o;
}

// ------------------- host launch (multi-stream fork/join, capture-safe) -------------------
extern "C" void kernel_launch(void* const* d_in, const int* in_sizes, int n_in,
                              void* d_out, int out_size)
{
    const float* x            = (const float*)d_in[0];
    const float* spatial_emb  = (const float*)d_in[1];
    const float* dtw_qkv_w    = (const float*)d_in[2];
    const float* dtw_qkv_b    = (const float*)d_in[3];
    const float* dtw_out_w    = (const float*)d_in[4];
    const float* dtw_out_b    = (const float*)d_in[5];
    const float* attn_qkv_w   = (const float*)d_in[6];
    const float* attn_qkv_b   = (const float*)d_in[7];
    const float* attn_out_w   = (const float*)d_in[8];
    const float* attn_out_b   = (const float*)d_in[9];
    const float* adp_pos      = (const float*)d_in[10];
    const float* gea_share_w  = (const float*)d_in[11];
    const float* gea_share_b  = (const float*)d_in[12];
    const float* gea_node_w   = (const float*)d_in[13];
    const float* gea_node_b   = (const float*)d_in[14];
    const float* gea_edge_w   = (const float*)d_in[15];
    const float* gea_edge_b   = (const float*)d_in[16];
    const float* spatial_w    = (const float*)d_in[17];
    const float* spatial_b    = (const float*)d_in[18];
    const float* ff1_w1       = (const float*)d_in[19];
    const float* ff1_b1       = (const float*)d_in[20];
    const float* ff1_w2       = (const float*)d_in[21];
    const float* ff1_b2       = (const float*)d_in[22];
    const float* ff2_w1       = (const float*)d_in[23];
    const float* ff2_b1       = (const float*)d_in[24];
    const float* ff2_w2       = (const float*)d_in[25];
    const float* ff2_b2       = (const float*)d_in[26];
    const float* ln_s         = (const float*)d_in[27];
    const float* ln_b         = (const float*)d_in[28];

    float* o_main = (float*)d_out;
    float* o_sen  = o_main + (size_t)M_ * D_;

    float *q1, *k1, *v1, *q2, *k2, *v2, *nodex, *pk, *pv, *ao1, *ao2;
    float *dtw, *oa, *extra, *sen, *esh, *senx, *outb, *ff, *oattn, *spin, *posT;
    cudaGetSymbolAddress((void**)&q1, g_q1);
    cudaGetSymbolAddress((void**)&k1, g_k1);
    cudaGetSymbolAddress((void**)&v1, g_v1);
    cudaGetSymbolAddress((void**)&q2, g_q2);
    cudaGetSymbolAddress((void**)&k2, g_k2);
    cudaGetSymbolAddress((void**)&v2, g_v2);
    cudaGetSymbolAddress((void**)&nodex, g_nodex);
    cudaGetSymbolAddress((void**)&pk, g_pk);
    cudaGetSymbolAddress((void**)&pv, g_pv);
    cudaGetSymbolAddress((void**)&ao1, g_ao1);
    cudaGetSymbolAddress((void**)&ao2, g_ao2);
    cudaGetSymbolAddress((void**)&dtw, g_dtw);
    cudaGetSymbolAddress((void**)&oa, g_oa);
    cudaGetSymbolAddress((void**)&extra, g_extra);
    cudaGetSymbolAddress((void**)&sen, g_sen);
    cudaGetSymbolAddress((void**)&esh, g_esh);
    cudaGetSymbolAddress((void**)&senx, g_senx);
    cudaGetSymbolAddress((void**)&outb, g_out);
    cudaGetSymbolAddress((void**)&ff, g_ff);
    cudaGetSymbolAddress((void**)&oattn, g_oattn);
    cudaGetSymbolAddress((void**)&spin, g_spin);
    cudaGetSymbolAddress((void**)&posT, g_posT);

    // one-time host-side setup (no device memory; identical GPU work every call)
    static cudaStream_t s1 = nullptr, s2 = nullptr, s3 = nullptr;
    static cudaEvent_t evStart = nullptr, ev0 = nullptr, ev1 = nullptr, ev2 = nullptr, ev3 = nullptr;
    if (!s1) {
        cudaStreamCreateWithFlags(&s1, cudaStreamNonBlocking);
        cudaStreamCreateWithFlags(&s2, cudaStreamNonBlocking);
        cudaStreamCreateWithFlags(&s3, cudaStreamNonBlocking);
        cudaEventCreateWithFlags(&evStart, cudaEventDisableTiming);
        cudaEventCreateWithFlags(&ev0, cudaEventDisableTiming);
        cudaEventCreateWithFlags(&ev1, cudaEventDisableTiming);
        cudaEventCreateWithFlags(&ev2, cudaEventDisableTiming);
        cudaEventCreateWithFlags(&ev3, cudaEventDisableTiming);
        cudaFuncSetAttribute(attn_full_mma, cudaFuncAttributeMaxDynamicSharedMemorySize,
                             AF_SMEM_W * 4);
    }

    int lnBlocksM = (M_ * 32 + 255) / 256;
    int lnBlocksS = (N_ * 32 + 255) / 256;
    dim3 gS(1, (N_ + 127) / 128);
    cudaStream_t s0 = 0;

    // fork point for the input-only sen path
    cudaEventRecord(evStart, s0);

    // s3: pos transpose + sen path (depends only on inputs)
    cudaStreamWaitEvent(s3, evStart, 0);
    pos_transpose_kernel<<<N_, C_, 0, s3>>>(adp_pos, posT);
    gemm_bias<false><<<gS, 256, 0, s3>>>(spatial_emb, spatial_w, spatial_b, esh, N_, D_, D_);
    ln_plain_kernel<<<lnBlocksS, 256, 0, s3>>>(esh, ln_s + 3 * D_, ln_b + 3 * D_, sen, N_);
    gemm_bias<false><<<gS, 256, 0, s3>>>(sen, gea_share_w, gea_share_b, esh, N_, D_, D_);
    gea_edge_kernel<<<(N_ + 31) / 32, 256, 0, s3>>>(esh, gea_edge_w, gea_edge_b, senx, o_sen);
    cudaEventRecord(ev3, s3);

    // s0: all 7 projections in one launch
    {
        GB gb = {};
        for (int z = 0; z < 7; z++) gb.A[z] = x;
        gb.Bm[0] = dtw_qkv_w + 0 * D_ * D_;  gb.bias[0] = dtw_qkv_b + 0 * D_;  gb.C[0] = q1;
        gb.Bm[1] = dtw_qkv_w + 1 * D_ * D_;  gb.bias[1] = dtw_qkv_b + 1 * D_;  gb.C[1] = k1;
        gb.Bm[2] = dtw_qkv_w + 2 * D_ * D_;  gb.bias[2] = dtw_qkv_b + 2 * D_;  gb.C[2] = v1;
        gb.Bm[3] = attn_qkv_w + 0 * D_ * D_; gb.bias[3] = attn_qkv_b + 0 * D_; gb.C[3] = q2;
        gb.Bm[4] = attn_qkv_w + 1 * D_ * D_; gb.bias[4] = attn_qkv_b + 1 * D_; gb.C[4] = k2;
        gb.Bm[5] = attn_qkv_w + 2 * D_ * D_; gb.bias[5] = attn_qkv_b + 2 * D_; gb.C[5] = v2;
        gb.Bm[6] = gea_share_w;              gb.bias[6] = gea_share_b;         gb.C[6] = nodex;
        gemm_tc<false><<<dim3(1, M_ / 128, 7), 256, 0, s0>>>(gb, M_, D_, D_);
    }
    cudaEventRecord(ev0, s0);

    // s1: dtw attention (longest independent branch)
    cudaStreamWaitEvent(s1, ev0, 0);
    attn_full_mma<<<dim3(4, BT_ * H_), 256, AF_SMEM_W * 4, s1>>>(q1, k1, v1, ao1);
    cudaEventRecord(ev1, s1);

    // s2: GEANet node path
    cudaStreamWaitEvent(s2, ev0, 0);
    gea_node_kernel<<<(B_ * N_ * T_ + 31) / 32, 256, 0, s2>>>(nodex, gea_node_w, gea_node_b, extra);
    cudaEventRecord(ev2, s2);

    // s0: pool + pooled attention (needs posT from s3)
    pool_kernel<<<BT_ * C_, 128, 0, s0>>>(k2, v2, pk, pv);
    cudaStreamWaitEvent(s0, ev3, 0);
    attn_pool_kernel<<<BT_ * H_, 256, 0, s0>>>(q2, pk, pv, posT, ao2);

    // join attn_full, then both output projections
    cudaStreamWaitEvent(s0, ev1, 0);
    {
        GB gb = {};
        gb.A[0] = ao1; gb.Bm[0] = dtw_out_w;  gb.bias[0] = dtw_out_b;  gb.C[0] = dtw;
        gb.A[1] = ao2; gb.Bm[1] = attn_out_w; gb.bias[1] = attn_out_b; gb.C[1] = oa;
        gemm_tc<false><<<dim3(1, M_ / 128, 2), 256, 0, s0>>>(gb, M_, D_, D_);
    }

    // join gea_node, then ln1
    cudaStreamWaitEvent(s0, ev2, 0);
    ln4_kernel<<<lnBlocksM, 256, 0, s0>>>(x, dtw, oa, extra, ln_s, ln_b, outb, M_);

    // FF1 + ln2 (+ spatial multiply) — serial chain on s0
    {
        GB gb = {};
        gb.A[0] = outb; gb.Bm[0] = ff1_w1; gb.bias[0] = ff1_b1; gb.C[0] = ff;
        gemm_tc<true><<<dim3(FF_ / 128, M_ / 128, 1), 256, 0, s0>>>(gb, M_, FF_, D_);
    }
    {
        GB gb = {};
        gb.A[0] = ff; gb.Bm[0] = ff1_w2; gb.bias[0] = ff1_b2; gb.C[0] = ao1;
        gemm_tc<false><<<dim3(1, M_ / 128, 1), 256, 0, s0>>>(gb, M_, D_, FF_);
    }
    ln2mul_kernel<<<lnBlocksM, 256, 0, s0>>>(ao1, outb, ln_s + D_, ln_b + D_, senx, oattn, spin, M_);

    // FF2 + spatial_norm + final add
    {
        GB gb = {};
        gb.A[0] = spin; gb.Bm[0] = ff2_w1; gb.bias[0] = ff2_b1; gb.C[0] = ff;
        gemm_tc<true><<<dim3(FF_ / 128, M_ / 128, 1), 256, 0, s0>>>(gb, M_, FF_, D_);
    }
    {
        GB gb = {};
        gb.A[0] = ff; gb.Bm[0] = ff2_w2; gb.bias[0] = ff2_b2; gb.C[0] = ao2;
        gemm_tc<false><<<dim3(1, M_ / 128, 1), 256, 0, s0>>>(gb, M_, D_, FF_);
    }
    ln_final_kernel<<<lnBlocksM, 256, 0, s0>>>(ao2, oattn, ln_s + 2 * D_, ln_b + 2 * D_, o_main, M_);
}